// round 4
// baseline (speedup 1.0000x reference)
#include <cuda_runtime.h>
#include <math.h>

#define LSEQ 262144
#define NMODE 64
#define TCH 64
#define NCHUNK (LSEQ / TCH)         // 4096
#define WPB 8
#define BTH 256
#define GRID_AC (NCHUNK / WPB)      // 512

typedef unsigned long long u64;

// Per-mode constants (double-precision setup)
__device__ float g_zre[NMODE],  g_zim[NMODE];   // z = exp(dt*A)
__device__ float g_z2re[NMODE], g_z2im[NMODE];  // z^2
__device__ float g_z4re[NMODE], g_z4im[NMODE];  // z^4
__device__ float g_cfre[NMODE], g_cfim[NMODE];  // coeff = Ct*(z-1)/A
__device__ float g_wre[NMODE],  g_wim[NMODE];   // w = z^TCH
__device__ float g_w4re[NMODE], g_w4im[NMODE];  // w^4
// Intermediates, [mode][chunk], interleaved complex for 16B access
__device__ __align__(16) float2 g_P[NMODE * NCHUNK];
__device__ __align__(16) float2 g_C[NMODE * NCHUNK];

// ---- packed f32x2 helpers ----
__device__ __forceinline__ u64 pk2(float lo, float hi) {
    u64 r; asm("mov.b64 %0, {%1,%2};" : "=l"(r) : "f"(lo), "f"(hi)); return r;
}
__device__ __forceinline__ void upk2(u64 v, float& lo, float& hi) {
    asm("mov.b64 {%0,%1}, %2;" : "=f"(lo), "=f"(hi) : "l"(v));
}
__device__ __forceinline__ u64 fma2(u64 a, u64 b, u64 c) {
    u64 d; asm("fma.rn.f32x2 %0, %1, %2, %3;" : "=l"(d) : "l"(a), "l"(b), "l"(c)); return d;
}
__device__ __forceinline__ u64 mul2(u64 a, u64 b) {
    u64 d; asm("mul.rn.f32x2 %0, %1, %2;" : "=l"(d) : "l"(a), "l"(b)); return d;
}

__global__ void setup_kernel(const float* __restrict__ A_re,
                             const float* __restrict__ A_im,
                             const float* __restrict__ C,
                             const float* __restrict__ log_step) {
    int n = threadIdx.x;
    if (n >= NMODE) return;
    double dt  = exp((double)log_step[0]);
    double ar  = (double)A_re[n], ai = (double)A_im[n];
    double dre = dt * ar, dim = dt * ai;
    double e   = exp(dre);
    double zre = e * cos(dim), zim = e * sin(dim);
    double nre = zre - 1.0, nim = zim;
    double inv = 1.0 / (ar * ar + ai * ai);
    double tre = (nre * ar + nim * ai) * inv;
    double tim = (nim * ar - nre * ai) * inv;
    double cr  = (double)C[2 * n], ci = (double)C[2 * n + 1];
    g_cfre[n] = (float)(cr * tre - ci * tim);
    g_cfim[n] = (float)(cr * tim + ci * tre);
    g_zre[n]  = (float)zre;
    g_zim[n]  = (float)zim;
    double e2 = exp(2.0 * dre);
    g_z2re[n] = (float)(e2 * cos(2.0 * dim));
    g_z2im[n] = (float)(e2 * sin(2.0 * dim));
    double e4 = exp(4.0 * dre);
    g_z4re[n] = (float)(e4 * cos(4.0 * dim));
    g_z4im[n] = (float)(e4 * sin(4.0 * dim));
    double ew = exp((double)TCH * dre), wa = (double)TCH * dim;
    g_wre[n]  = (float)(ew * cos(wa));
    g_wim[n]  = (float)(ew * sin(wa));
    double ew4 = exp(4.0 * (double)TCH * dre), wa4 = 4.0 * (double)TCH * dim;
    g_w4re[n]  = (float)(ew4 * cos(wa4));
    g_w4im[n]  = (float)(ew4 * sin(wa4));
}

// Phase 1: per-chunk recurrence, 4-step unrolled (chain = 2 dep FFMA2 / 4 elems).
__global__ __launch_bounds__(BTH) void partial_kernel(const float* __restrict__ u) {
    __shared__ __align__(16) float su[WPB * TCH];
    __shared__ __align__(16) float2 sP[NMODE][WPB];
    int tid  = threadIdx.x;
    int base = blockIdx.x * (WPB * TCH);
    ((float2*)su)[tid] = ((const float2*)(u + base))[tid];
    __syncthreads();

    int warp = tid >> 5, lane = tid & 31;
    u64 zr  = pk2(g_zre[lane],  g_zre[lane + 32]);
    u64 zi  = pk2(g_zim[lane],  g_zim[lane + 32]);
    u64 z2r = pk2(g_z2re[lane], g_z2re[lane + 32]);
    float a0 = g_z2im[lane], a1 = g_z2im[lane + 32];
    u64 z2i = pk2(a0, a1), nz2i = pk2(-a0, -a1);
    u64 z4r = pk2(g_z4re[lane], g_z4re[lane + 32]);
    float b0 = g_z4im[lane], b1 = g_z4im[lane + 32];
    u64 z4i = pk2(b0, b1), nz4i = pk2(-b0, -b1);
    u64 sr = pk2(0.f, 0.f), si = pk2(0.f, 0.f);
    const float4* uw = (const float4*)&su[warp * TCH];
#pragma unroll
    for (int i = 0; i < TCH / 4; i++) {
        float4 uu = uw[i];
        u64 u1p = pk2(uu.x, uu.x), u2p = pk2(uu.y, uu.y);
        u64 u3p = pk2(uu.z, uu.z), u4p = pk2(uu.w, uu.w);
        u64 t1r = fma2(zr, u1p, u2p), t1i = mul2(zi, u1p);
        u64 t2r = fma2(zr, u3p, u4p), t2i = mul2(zi, u3p);
        u64 br = fma2(z2r, t1r, fma2(nz2i, t1i, t2r));
        u64 bi = fma2(z2i, t1r, fma2(z2r, t1i, t2i));
        u64 nr = fma2(z4r, sr, fma2(nz4i, si, br));
        u64 ni = fma2(z4i, sr, fma2(z4r, si, bi));
        sr = nr; si = ni;
    }
    float s0r, s1r, s0i, s1i;
    upk2(sr, s0r, s1r); upk2(si, s0i, s1i);
    sP[lane][warp]      = make_float2(s0r, s0i);
    sP[lane + 32][warp] = make_float2(s1r, s1i);
    __syncthreads();
    int row = tid >> 2, col = (tid & 3) * 2;
    int c0  = blockIdx.x * WPB;
    *(float4*)&g_P[row * NCHUNK + c0 + col] = *(const float4*)&sP[row][col];
}

// Phase 2: per-mode scan over 4096 chunk partials; fold 4 (Horner w), scan W=w^4.
__global__ __launch_bounds__(1024) void scan_kernel() {
    __shared__ float sre[1024], sim_[1024];
    int mode = blockIdx.x, t = threadIdx.x;
    float wr = g_wre[mode], wi = g_wim[mode];
    const float2* P = &g_P[mode * NCHUNK];
    float4 pa = *(const float4*)&P[4 * t];
    float4 pb = *(const float4*)&P[4 * t + 2];
    float p0r = pa.x, p0i = pa.y, p1r = pa.z, p1i = pa.w;
    float p2r = pb.x, p2i = pb.y, p3r = pb.z, p3i = pb.w;
    float vr = p0r, vi = p0i, nr, ni;
    nr = fmaf(wr, vr, fmaf(-wi, vi, p1r));
    ni = fmaf(wi, vr, fmaf( wr, vi, p1i)); vr = nr; vi = ni;
    nr = fmaf(wr, vr, fmaf(-wi, vi, p2r));
    ni = fmaf(wi, vr, fmaf( wr, vi, p2i)); vr = nr; vi = ni;
    nr = fmaf(wr, vr, fmaf(-wi, vi, p3r));
    ni = fmaf(wi, vr, fmaf( wr, vi, p3i)); vr = nr; vi = ni;
    sre[t] = vr; sim_[t] = vi;
    float cwr = g_w4re[mode], cwi = g_w4im[mode];
    __syncthreads();
    for (int k = 1; k < 1024; k <<= 1) {
        float ore = 0.f, oim = 0.f;
        if (t >= k) { ore = sre[t - k]; oim = sim_[t - k]; }
        __syncthreads();
        vr += cwr * ore - cwi * oim;
        vi += cwr * oim + cwi * ore;
        sre[t] = vr; sim_[t] = vi;
        float nwr = cwr * cwr - cwi * cwi;
        cwi = 2.f * cwr * cwi; cwr = nwr;
        __syncthreads();
    }
    float e0r = 0.f, e0i = 0.f;
    if (t > 0) { e0r = sre[t - 1]; e0i = sim_[t - 1]; }
    float e1r = fmaf(wr, e0r, fmaf(-wi, e0i, p0r));
    float e1i = fmaf(wi, e0r, fmaf( wr, e0i, p0i));
    float e2r = fmaf(wr, e1r, fmaf(-wi, e1i, p1r));
    float e2i = fmaf(wi, e1r, fmaf( wr, e1i, p1i));
    float e3r = fmaf(wr, e2r, fmaf(-wi, e2i, p2r));
    float e3i = fmaf(wi, e2r, fmaf( wr, e2i, p2i));
    float2* Cp = &g_C[mode * NCHUNK + 4 * t];
    *(float4*)&Cp[0] = make_float4(e0r, e0i, e1r, e1i);
    *(float4*)&Cp[2] = make_float4(e2r, e2i, e3r, e3i);
}

// Phase 3: carry-seeded recurrence, 4-step unrolled, transpose-reduce, emit y.
__global__ __launch_bounds__(BTH) void output_kernel(const float* __restrict__ u,
                                                     const float* __restrict__ D,
                                                     float* __restrict__ y) {
    __shared__ __align__(16) float su[WPB * TCH];
    __shared__ __align__(16) float2 sC[NMODE][WPB];
    __shared__ __align__(16) float red[WPB][32 * 34];
    int tid  = threadIdx.x;
    int base = blockIdx.x * (WPB * TCH);
    ((float2*)su)[tid] = ((const float2*)(u + base))[tid];
    {
        int row = tid >> 2, col = (tid & 3) * 2;
        int c0  = blockIdx.x * WPB;
        *(float4*)&sC[row][col] = *(const float4*)&g_C[row * NCHUNK + c0 + col];
    }
    __syncthreads();

    int warp = tid >> 5, lane = tid & 31;
    u64 zr  = pk2(g_zre[lane],  g_zre[lane + 32]);
    float c0_ = g_zim[lane], c1_ = g_zim[lane + 32];
    u64 zi  = pk2(c0_, c1_), nzi = pk2(-c0_, -c1_);
    u64 z2r = pk2(g_z2re[lane], g_z2re[lane + 32]);
    float a0 = g_z2im[lane], a1 = g_z2im[lane + 32];
    u64 z2i = pk2(a0, a1), nz2i = pk2(-a0, -a1);
    u64 fr  = pk2(g_cfre[lane], g_cfre[lane + 32]);
    float fi0 = g_cfim[lane], fi1 = g_cfim[lane + 32];
    u64 nfi = pk2(-fi0, -fi1);
    float2 car0 = sC[lane][warp], car1 = sC[lane + 32][warp];
    u64 sr = pk2(car0.x, car1.x), si = pk2(car0.y, car1.y);
    float Dv = D[0];
    const float4* uw = (const float4*)&su[warp * TCH];
    float* rw = &red[warp][0];
    int gbase = base + warp * TCH;

#pragma unroll
    for (int tile = 0; tile < TCH / 32; tile++) {
#pragma unroll
        for (int i = 0; i < 32; i += 4) {
            float4 uu = uw[(tile * 32 + i) >> 2];
            u64 u1p = pk2(uu.x, uu.x), u2p = pk2(uu.y, uu.y);
            u64 u3p = pk2(uu.z, uu.z), u4p = pk2(uu.w, uu.w);
            u64 t1r = fma2(zr, u1p, u2p), t1i = mul2(zi, u1p);
            u64 t2r = fma2(zr, u3p, u4p), t2i = mul2(zi, u3p);
            // s1 = z*s + u1   (off carried chain)
            u64 s1r = fma2(zr, sr, fma2(nzi, si, u1p));
            u64 s1i = fma2(zi, sr, mul2(zr, si));
            // s2 = z^2*s + t1  (carried chain step 1)
            u64 s2r = fma2(z2r, sr, fma2(nz2i, si, t1r));
            u64 s2i = fma2(z2i, sr, fma2(z2r, si, t1i));
            // s3 = z*s2 + u3   (off chain)
            u64 s3r = fma2(zr, s2r, fma2(nzi, s2i, u3p));
            u64 s3i = fma2(zi, s2r, mul2(zr, s2i));
            // s4 = z^2*s2 + t2 (carried chain step 2)
            u64 s4r = fma2(z2r, s2r, fma2(nz2i, s2i, t2r));
            u64 s4i = fma2(z2i, s2r, fma2(z2r, s2i, t2i));
            sr = s4r; si = s4i;
            // contributions Re(coeff*s_k) per lane (2 modes packed)
            u64 cp1 = fma2(fr, s1r, mul2(nfi, s1i));
            u64 cp2 = fma2(fr, s2r, mul2(nfi, s2i));
            u64 cp3 = fma2(fr, s3r, mul2(nfi, s3i));
            u64 cp4 = fma2(fr, s4r, mul2(nfi, s4i));
            float x0, x1, y0, y1, w0, w1, v0, v1;
            upk2(cp1, x0, x1); upk2(cp2, y0, y1);
            upk2(cp3, w0, w1); upk2(cp4, v0, v1);
            *(float2*)&rw[lane * 34 + i]     = make_float2(x0 + x1, y0 + y1);
            *(float2*)&rw[lane * 34 + i + 2] = make_float2(w0 + w1, v0 + v1);
        }
        __syncwarp();
        float acc = 0.f;
#pragma unroll
        for (int l = 0; l < 32; l++) acc += rw[l * 34 + lane];
        float uv = su[warp * TCH + tile * 32 + lane];
        y[gbase + tile * 32 + lane] = fmaf(Dv, uv, acc);
        __syncwarp();
    }
}

extern "C" void kernel_launch(void* const* d_in, const int* in_sizes, int n_in,
                              void* d_out, int out_size) {
    const float* u        = (const float*)d_in[0];
    const float* A_re     = (const float*)d_in[1];
    const float* A_im     = (const float*)d_in[2];
    const float* C        = (const float*)d_in[3];
    const float* D        = (const float*)d_in[4];
    const float* log_step = (const float*)d_in[5];
    float* y = (float*)d_out;

    setup_kernel<<<1, NMODE>>>(A_re, A_im, C, log_step);
    partial_kernel<<<GRID_AC, BTH>>>(u);
    scan_kernel<<<NMODE, 1024>>>();
    output_kernel<<<GRID_AC, BTH>>>(u, D, y);
}